// round 10
// baseline (speedup 1.0000x reference)
#include <cuda_runtime.h>
#include <cuda_fp16.h>
#include <math.h>

// ---------------- problem constants (fixed by the dataset) ----------------
#define NODES 100000
#define FEAT  64
#define EDGES 800000
#define SAMP  25000
#define HID   128

// ---------------- scratch (device globals; no allocation) ----------------
__device__ float  d_q [(size_t)NODES * 128];   // W1^T x + b  (fp32)
__device__ __half d_pv[(size_t)NODES * 128];   // W2^T x      (fp16, hot random stream)
__device__ float  d_agg[(size_t)NODES * 128];  // per-node max-aggregated activations
__device__ int    d_cnt[NODES];
__device__ int    d_off[NODES];
__device__ int    d_cur[NODES];
__device__ int    d_src[EDGES];
__device__ int    d_bsum[128];

// ---------------- counting sort of edges by target node ----------------
__global__ void k_zero_cnt(int n) {
    int i = blockIdx.x * blockDim.x + threadIdx.x;
    if (i < n) d_cnt[i] = 0;
}

__global__ void k_hist(const int* __restrict__ row, int E) {
    int i = blockIdx.x * blockDim.x + threadIdx.x;
    if (i < E) atomicAdd(&d_cnt[row[i]], 1);
}

__global__ void k_scan1(int n) {  // per-1024-block inclusive scan, block sums out
    __shared__ int sm[1024];
    int i = blockIdx.x * 1024 + threadIdx.x;
    int v = (i < n) ? d_cnt[i] : 0;
    sm[threadIdx.x] = v;
    __syncthreads();
    for (int d = 1; d < 1024; d <<= 1) {
        int t = 0;
        if (threadIdx.x >= d) t = sm[threadIdx.x - d];
        __syncthreads();
        if (threadIdx.x >= d) sm[threadIdx.x] += t;
        __syncthreads();
    }
    if (i < n) d_off[i] = sm[threadIdx.x];            // inclusive for now
    if (threadIdx.x == 1023) d_bsum[blockIdx.x] = sm[1023];
}

__global__ void k_scan2(int nb) {  // exclusive scan of <=128 block sums (1 block)
    __shared__ int sm[128];
    int t = threadIdx.x;
    int v = (t < nb) ? d_bsum[t] : 0;
    sm[t] = v;
    __syncthreads();
    for (int d = 1; d < 128; d <<= 1) {
        int u = 0;
        if (t >= d) u = sm[t - d];
        __syncthreads();
        if (t >= d) sm[t] += u;
        __syncthreads();
    }
    if (t < nb) d_bsum[t] = sm[t] - v;  // exclusive
}

__global__ void k_scan3(int n) {  // finalize exclusive offsets + scatter cursor
    int i = blockIdx.x * blockDim.x + threadIdx.x;
    if (i < n) {
        int e = d_off[i] - d_cnt[i] + d_bsum[i >> 10];
        d_off[i] = e;
        d_cur[i] = e;
    }
}

__global__ void k_scatter(const int* __restrict__ col, const int* __restrict__ row, int E) {
    int i = blockIdx.x * blockDim.x + threadIdx.x;
    if (i < E) {
        int t = row[i];
        int p = atomicAdd(&d_cur[t], 1);
        d_src[p] = col[i];
    }
}

// ---------------- fused tf32 tensor-core GEMM: [64-row tile, K=64] x [64, 256] --------
// B[k][j] = (j<128) ? W[k][j] : W[64+k][j-128].
// cols 0..127 -> d_q (fp32, +bias), cols 128..255 -> d_pv (fp16).
// smem: As[64][68] fp32(tf32-rounded), Bs[64][264] -> conflict-free fragment LDS.
#define A_STRIDE 68
#define B_STRIDE 264
#define GEMM_SMEM ((64 * A_STRIDE + 64 * B_STRIDE) * 4)

__device__ __forceinline__ unsigned tf32r(float f) {
    unsigned u;
    asm("cvt.rna.tf32.f32 %0, %1;" : "=r"(u) : "f"(f));
    return u;
}

__device__ __forceinline__ void mma_tf32(float& c0, float& c1, float& c2, float& c3,
                                         unsigned a0, unsigned a1, unsigned a2, unsigned a3,
                                         unsigned b0, unsigned b1) {
    asm volatile(
        "mma.sync.aligned.m16n8k8.row.col.f32.tf32.tf32.f32 "
        "{%0,%1,%2,%3}, {%4,%5,%6,%7}, {%8,%9}, {%0,%1,%2,%3};"
        : "+f"(c0), "+f"(c1), "+f"(c2), "+f"(c3)
        : "r"(a0), "r"(a1), "r"(a2), "r"(a3), "r"(b0), "r"(b1));
}

__global__ void __launch_bounds__(256)
k_gemm(const float* __restrict__ x, const float* __restrict__ Wm,
       const float* __restrict__ bv, int N) {
    extern __shared__ unsigned smem[];
    unsigned* As = smem;                     // [64][A_STRIDE]
    unsigned* Bs = smem + 64 * A_STRIDE;     // [64][B_STRIDE]
    int tid = threadIdx.x;
    int blk_row0 = blockIdx.x * 64;

    {   // A tile: 64 rows x 64 feats, tf32-rounded, row-major
        int r = tid >> 2;
        bool ok = (blk_row0 + r) < N;
        const float* xp = x + (size_t)(blk_row0 + r) * FEAT;
#pragma unroll
        for (int i = 0; i < 4; i++) {
            int c = (tid & 3) * 16 + i * 4;
            float4 v = ok ? *(const float4*)(xp + c) : make_float4(0.f, 0.f, 0.f, 0.f);
            unsigned* dst = &As[r * A_STRIDE + c];
            dst[0] = tf32r(v.x); dst[1] = tf32r(v.y);
            dst[2] = tf32r(v.z); dst[3] = tf32r(v.w);
        }
    }
    {   // B tile: 64 x 256 assembled from W rows [0:64) and [64:128)
#pragma unroll
        for (int it = 0; it < 16; it++) {
            int v = tid + 256 * it;          // 0..4095 float4 slots
            int k = v >> 6;
            int j0 = (v & 63) * 4;
            const float* src = (j0 < 128) ? (Wm + k * 128 + j0)
                                          : (Wm + (64 + k) * 128 + (j0 - 128));
            float4 w4 = *(const float4*)src;
            unsigned* dst = &Bs[k * B_STRIDE + j0];
            dst[0] = tf32r(w4.x); dst[1] = tf32r(w4.y);
            dst[2] = tf32r(w4.z); dst[3] = tf32r(w4.w);
        }
    }
    __syncthreads();

    int wid = tid >> 5;
    int lane = tid & 31;
    int row0 = (wid >> 2) * 32;      // 0 or 32
    int col0 = (wid & 3) * 64;       // 0,64,128,192
    int lr = lane >> 2;              // 0..7
    int lc = lane & 3;               // 0..3

    float c[2][8][4];
#pragma unroll
    for (int mt = 0; mt < 2; mt++)
#pragma unroll
        for (int nt = 0; nt < 8; nt++)
#pragma unroll
            for (int e = 0; e < 4; e++) c[mt][nt][e] = 0.f;

#pragma unroll
    for (int k0 = 0; k0 < 64; k0 += 8) {
        unsigned a[2][4], b[8][2];
#pragma unroll
        for (int mt = 0; mt < 2; mt++) {
            int ra = row0 + mt * 16 + lr;
            a[mt][0] = As[ra * A_STRIDE + k0 + lc];
            a[mt][1] = As[(ra + 8) * A_STRIDE + k0 + lc];
            a[mt][2] = As[ra * A_STRIDE + k0 + lc + 4];
            a[mt][3] = As[(ra + 8) * A_STRIDE + k0 + lc + 4];
        }
#pragma unroll
        for (int nt = 0; nt < 8; nt++) {
            int cb = col0 + nt * 8 + lr;
            b[nt][0] = Bs[(k0 + lc) * B_STRIDE + cb];
            b[nt][1] = Bs[(k0 + lc + 4) * B_STRIDE + cb];
        }
#pragma unroll
        for (int mt = 0; mt < 2; mt++)
#pragma unroll
            for (int nt = 0; nt < 8; nt++)
                mma_tf32(c[mt][nt][0], c[mt][nt][1], c[mt][nt][2], c[mt][nt][3],
                         a[mt][0], a[mt][1], a[mt][2], a[mt][3],
                         b[nt][0], b[nt][1]);
    }

    // epilogue: C frag (mt,nt): rows row0+mt*16+lr (+8), cols col0+nt*8+2*lc (+1)
    bool is_q = (col0 < 128);
#pragma unroll
    for (int mt = 0; mt < 2; mt++) {
        int r_lo = blk_row0 + row0 + mt * 16 + lr;
        int r_hi = r_lo + 8;
#pragma unroll
        for (int nt = 0; nt < 8; nt++) {
            int cc = col0 + nt * 8 + 2 * lc;
            if (is_q) {
                float2 bb = *(const float2*)&bv[cc];
                if (r_lo < N)
                    *(float2*)&d_q[(size_t)r_lo * 128 + cc] =
                        make_float2(c[mt][nt][0] + bb.x, c[mt][nt][1] + bb.y);
                if (r_hi < N)
                    *(float2*)&d_q[(size_t)r_hi * 128 + cc] =
                        make_float2(c[mt][nt][2] + bb.x, c[mt][nt][3] + bb.y);
            } else {
                int cp = cc - 128;
                if (r_lo < N) {
                    __half2 h = __floats2half2_rn(c[mt][nt][0], c[mt][nt][1]);
                    *(unsigned*)&d_pv[(size_t)r_lo * 128 + cp] = *(unsigned*)&h;
                }
                if (r_hi < N) {
                    __half2 h = __floats2half2_rn(c[mt][nt][2], c[mt][nt][3]);
                    *(unsigned*)&d_pv[(size_t)r_hi * 128 + cp] = *(unsigned*)&h;
                }
            }
        }
    }
}

// ---------------- edge aggregation: one warp per target node ----------------
__device__ __forceinline__ float angle3(float ax, float ay, float az,
                                        float bx, float by, float bz) {
    float cx = ay * bz - az * by;
    float cy = az * bx - ax * bz;
    float cz = ax * by - ay * bx;
    float cn = sqrtf(cx * cx + cy * cy + cz * cz);
    float d = ax * bx + ay * by + az * bz;
    return atan2f(cn, d);
}

__global__ void k_agg(const float* __restrict__ pos, const float* __restrict__ nor,
                      const float* __restrict__ Wm, int N) {
    int w = (blockIdx.x * blockDim.x + threadIdx.x) >> 5;
    if (w >= N) return;
    int cnt = d_cnt[w];
    if (cnt == 0) return;
    int lane = threadIdx.x & 31;
    int start = d_off[w];
    int end = start + cnt;
    int col = lane * 4;

    float4 w0 = *(const float4*)&Wm[128 * 128 + col];           // ppf weight rows
    float4 w1 = *(const float4*)&Wm[129 * 128 + col];
    float4 w2 = *(const float4*)&Wm[130 * 128 + col];
    float4 w3 = *(const float4*)&Wm[131 * 128 + col];
    float ptx = pos[3 * w], pty = pos[3 * w + 1], ptz = pos[3 * w + 2];
    float ntx = nor[3 * w], nty = nor[3 * w + 1], ntz = nor[3 * w + 2];
    // q folded out of the loop: relu(q + max_s(pv + g.w)) == max(0, q + M)
    float4 m = make_float4(-3e38f, -3e38f, -3e38f, -3e38f);

    for (int base = start; base < end; base += 32) {
        int j = base + lane;
        int s = 0;
        float f0 = 0.f, f1 = 0.f, f2 = 0.f, f3 = 0.f;
        if (j < end) {
            s = d_src[j];
            float px = pos[3 * s] - ptx;
            float py = pos[3 * s + 1] - pty;
            float pz = pos[3 * s + 2] - ptz;
            float nsx = nor[3 * s], nsy = nor[3 * s + 1], nsz = nor[3 * s + 2];
            f0 = sqrtf(px * px + py * py + pz * pz);
            f1 = angle3(ntx, nty, ntz, px, py, pz);    // angle(n1, pseudo)
            f2 = angle3(nsx, nsy, nsz, px, py, pz);    // angle(n0, pseudo)
            f3 = angle3(ntx, nty, ntz, nsx, nsy, nsz); // angle(n1, n0)
        }
        int c32 = end - base;
        if (c32 > 32) c32 = 32;
        for (int i = 0; i < c32; i++) {
            int si  = __shfl_sync(0xffffffffu, s, i);
            float g0 = __shfl_sync(0xffffffffu, f0, i);
            float g1 = __shfl_sync(0xffffffffu, f1, i);
            float g2 = __shfl_sync(0xffffffffu, f2, i);
            float g3 = __shfl_sync(0xffffffffu, f3, i);
            uint2 hv = *(const uint2*)&d_pv[(size_t)si * 128 + col];  // 4 halves, 8B
            float2 p01 = __half22float2(*(const __half2*)&hv.x);
            float2 p23 = __half22float2(*(const __half2*)&hv.y);
            float z0 = p01.x, z1 = p01.y, z2 = p23.x, z3 = p23.y;
            z0 = fmaf(g0, w0.x, z0); z1 = fmaf(g0, w0.y, z1); z2 = fmaf(g0, w0.z, z2); z3 = fmaf(g0, w0.w, z3);
            z0 = fmaf(g1, w1.x, z0); z1 = fmaf(g1, w1.y, z1); z2 = fmaf(g1, w1.z, z2); z3 = fmaf(g1, w1.w, z3);
            z0 = fmaf(g2, w2.x, z0); z1 = fmaf(g2, w2.y, z1); z2 = fmaf(g2, w2.z, z2); z3 = fmaf(g2, w2.w, z3);
            z0 = fmaf(g3, w3.x, z0); z1 = fmaf(g3, w3.y, z1); z2 = fmaf(g3, w3.z, z2); z3 = fmaf(g3, w3.w, z3);
            m.x = fmaxf(m.x, z0); m.y = fmaxf(m.y, z1);
            m.z = fmaxf(m.z, z2); m.w = fmaxf(m.w, z3);
        }
    }
    float4 q = *(const float4*)&d_q[(size_t)w * 128 + col];
    m.x = fmaxf(q.x + m.x, 0.f);
    m.y = fmaxf(q.y + m.y, 0.f);
    m.z = fmaxf(q.z + m.z, 0.f);
    m.w = fmaxf(q.w + m.w, 0.f);
    *(float4*)&d_agg[(size_t)w * 128 + col] = m;
}

// ---------------- gather: out[s] = agg[idx[s]] (0 if no edges), pos_out ----------------
__global__ void k_gather(const float* __restrict__ pos, const int* __restrict__ idx,
                         float* __restrict__ out, int S) {
    int s = blockIdx.x;
    int h = threadIdx.x;  // 128
    int t = idx[s];
    float v = d_cnt[t] ? d_agg[(size_t)t * 128 + h] : 0.f;
    out[(size_t)s * 128 + h] = v;
    if (h < 3) out[(size_t)S * 128 + (size_t)s * 3 + h] = pos[3 * t + h];
}

// ---------------- launch (gemm on side stream || sort chain) ----------------
extern "C" void kernel_launch(void* const* d_in, const int* in_sizes, int n_in,
                              void* d_out, int out_size) {
    const float *x = 0, *pos = 0, *nor = 0, *Wm = 0, *bv = 0;
    const int *edge = 0, *idx = 0;
    for (int i = 0; i < n_in; i++) {
        int sz = in_sizes[i];
        if (sz == NODES * FEAT) x = (const float*)d_in[i];
        else if (sz == NODES * 3) { if (!pos) pos = (const float*)d_in[i]; else nor = (const float*)d_in[i]; }
        else if (sz == (2 * FEAT + 4) * HID) Wm = (const float*)d_in[i];
        else if (sz == HID) bv = (const float*)d_in[i];
        else if (sz == 2 * EDGES) edge = (const int*)d_in[i];
        else if (sz == SAMP) idx = (const int*)d_in[i];
    }
    const int* ecol = edge;          // e0 (sources)
    const int* erow = edge + EDGES;  // e1 (targets)

    static cudaStream_t sB = 0;
    static cudaEvent_t eFork = 0, ePv = 0;
    if (!sB) {
        cudaStreamCreateWithFlags(&sB, cudaStreamNonBlocking);
        cudaEventCreateWithFlags(&eFork, cudaEventDisableTiming);
        cudaEventCreateWithFlags(&ePv,   cudaEventDisableTiming);
        cudaFuncSetAttribute(k_gemm, cudaFuncAttributeMaxDynamicSharedMemorySize, GEMM_SMEM);
    }

    int nb = (NODES + 1023) / 1024;

    // fork: tensor-core gemm on sB, independent of the sort chain
    cudaEventRecord(eFork, 0);
    cudaStreamWaitEvent(sB, eFork, 0);
    k_gemm<<<(NODES + 63) / 64, 256, GEMM_SMEM, sB>>>(x, Wm, bv, NODES);
    cudaEventRecord(ePv, sB);

    // sort chain on the main stream
    k_zero_cnt<<<(NODES + 255) / 256, 256>>>(NODES);
    k_hist<<<(EDGES + 255) / 256, 256>>>(erow, EDGES);
    k_scan1<<<nb, 1024>>>(NODES);
    k_scan2<<<1, 128>>>(nb);
    k_scan3<<<(NODES + 255) / 256, 256>>>(NODES);
    k_scatter<<<(EDGES + 255) / 256, 256>>>(ecol, erow, EDGES);

    // join: agg needs scatter (main) + gemm (sB)
    cudaStreamWaitEvent(0, ePv, 0);
    k_agg<<<(NODES + 7) / 8, 256>>>(pos, nor, Wm, NODES);
    k_gather<<<SAMP, 128>>>(pos, idx, (float*)d_out, SAMP);
}

// round 12
// speedup vs baseline: 1.0841x; 1.0841x over previous
#include <cuda_runtime.h>
#include <cuda_fp16.h>
#include <math.h>

// ---------------- problem constants (fixed by the dataset) ----------------
#define NODES 100000
#define FEAT  64
#define EDGES 800000
#define SAMP  25000
#define HID   128

// ---------------- scratch (device globals; no allocation) ----------------
__device__ float  d_q [(size_t)NODES * 128];   // W1^T x + b  (fp32)
__device__ __half d_pv[(size_t)NODES * 128];   // W2^T x      (fp16, hot random stream)
__device__ float  d_agg[(size_t)NODES * 128];  // per-node max-aggregated activations
__device__ int    d_cnt[NODES];
__device__ int    d_off[NODES];
__device__ int    d_cur[NODES];
__device__ int    d_src[EDGES];
__device__ uint2  d_ppf[EDGES];                // packed half4 ppf, sorted by target
__device__ int    d_bsum[128];

// ---------------- counting sort of edges by target node ----------------
__global__ void k_zero_cnt(int n) {
    int i = blockIdx.x * blockDim.x + threadIdx.x;
    if (i < n) d_cnt[i] = 0;
}

__global__ void k_hist(const int* __restrict__ row, int E) {
    int i = blockIdx.x * blockDim.x + threadIdx.x;
    if (i < E) atomicAdd(&d_cnt[row[i]], 1);
}

__global__ void k_scan1(int n) {  // per-1024-block inclusive scan, block sums out
    __shared__ int sm[1024];
    int i = blockIdx.x * 1024 + threadIdx.x;
    int v = (i < n) ? d_cnt[i] : 0;
    sm[threadIdx.x] = v;
    __syncthreads();
    for (int d = 1; d < 1024; d <<= 1) {
        int t = 0;
        if (threadIdx.x >= d) t = sm[threadIdx.x - d];
        __syncthreads();
        if (threadIdx.x >= d) sm[threadIdx.x] += t;
        __syncthreads();
    }
    if (i < n) d_off[i] = sm[threadIdx.x];            // inclusive for now
    if (threadIdx.x == 1023) d_bsum[blockIdx.x] = sm[1023];
}

__global__ void k_scan2(int nb) {  // exclusive scan of <=128 block sums (1 block)
    __shared__ int sm[128];
    int t = threadIdx.x;
    int v = (t < nb) ? d_bsum[t] : 0;
    sm[t] = v;
    __syncthreads();
    for (int d = 1; d < 128; d <<= 1) {
        int u = 0;
        if (t >= d) u = sm[t - d];
        __syncthreads();
        if (t >= d) sm[t] += u;
        __syncthreads();
    }
    if (t < nb) d_bsum[t] = sm[t] - v;  // exclusive
}

__global__ void k_scan3(int n) {  // finalize exclusive offsets + scatter cursor
    int i = blockIdx.x * blockDim.x + threadIdx.x;
    if (i < n) {
        int e = d_off[i] - d_cnt[i] + d_bsum[i >> 10];
        d_off[i] = e;
        d_cur[i] = e;
    }
}

// ---------------- scatter + fused ppf (edge-parallel; atan2f fully parallel here) -----
__device__ __forceinline__ float angle3(float ax, float ay, float az,
                                        float bx, float by, float bz) {
    float cx = ay * bz - az * by;
    float cy = az * bx - ax * bz;
    float cz = ax * by - ay * bx;
    float cn = sqrtf(cx * cx + cy * cy + cz * cz);
    float d = ax * bx + ay * by + az * bz;
    return atan2f(cn, d);
}

__global__ void k_scatter(const int* __restrict__ col, const int* __restrict__ row,
                          const float* __restrict__ pos, const float* __restrict__ nor,
                          int E) {
    int i = blockIdx.x * blockDim.x + threadIdx.x;
    if (i >= E) return;
    int t = row[i];
    int s = col[i];
    float px = pos[3 * s]     - pos[3 * t];
    float py = pos[3 * s + 1] - pos[3 * t + 1];
    float pz = pos[3 * s + 2] - pos[3 * t + 2];
    float nsx = nor[3 * s], nsy = nor[3 * s + 1], nsz = nor[3 * s + 2];
    float ntx = nor[3 * t], nty = nor[3 * t + 1], ntz = nor[3 * t + 2];
    float f0 = sqrtf(px * px + py * py + pz * pz);
    float f1 = angle3(ntx, nty, ntz, px, py, pz);    // angle(n1, pseudo)
    float f2 = angle3(nsx, nsy, nsz, px, py, pz);    // angle(n0, pseudo)
    float f3 = angle3(ntx, nty, ntz, nsx, nsy, nsz); // angle(n1, n0)
    __half2 h01 = __floats2half2_rn(f0, f1);
    __half2 h23 = __floats2half2_rn(f2, f3);
    int p = atomicAdd(&d_cur[t], 1);
    d_src[p] = s;
    d_ppf[p] = make_uint2(*(unsigned*)&h01, *(unsigned*)&h23);
}

// ---------------- fused tf32 tensor-core GEMM: [64-row tile, K=64] x [64, 256] --------
// B[k][j] = (j<128) ? W[k][j] : W[64+k][j-128].
// cols 0..127 -> d_q (fp32, +bias), cols 128..255 -> d_pv (fp16).
#define A_STRIDE 68
#define B_STRIDE 264
#define GEMM_SMEM ((64 * A_STRIDE + 64 * B_STRIDE) * 4)

__device__ __forceinline__ unsigned tf32r(float f) {
    unsigned u;
    asm("cvt.rna.tf32.f32 %0, %1;" : "=r"(u) : "f"(f));
    return u;
}

__device__ __forceinline__ void mma_tf32(float& c0, float& c1, float& c2, float& c3,
                                         unsigned a0, unsigned a1, unsigned a2, unsigned a3,
                                         unsigned b0, unsigned b1) {
    asm volatile(
        "mma.sync.aligned.m16n8k8.row.col.f32.tf32.tf32.f32 "
        "{%0,%1,%2,%3}, {%4,%5,%6,%7}, {%8,%9}, {%0,%1,%2,%3};"
        : "+f"(c0), "+f"(c1), "+f"(c2), "+f"(c3)
        : "r"(a0), "r"(a1), "r"(a2), "r"(a3), "r"(b0), "r"(b1));
}

__global__ void __launch_bounds__(256)
k_gemm(const float* __restrict__ x, const float* __restrict__ Wm,
       const float* __restrict__ bv, int N) {
    extern __shared__ unsigned smem[];
    unsigned* As = smem;                     // [64][A_STRIDE]
    unsigned* Bs = smem + 64 * A_STRIDE;     // [64][B_STRIDE]
    int tid = threadIdx.x;
    int blk_row0 = blockIdx.x * 64;

    {   // A tile: 64 rows x 64 feats, tf32-rounded, row-major
        int r = tid >> 2;
        bool ok = (blk_row0 + r) < N;
        const float* xp = x + (size_t)(blk_row0 + r) * FEAT;
#pragma unroll
        for (int i = 0; i < 4; i++) {
            int c = (tid & 3) * 16 + i * 4;
            float4 v = ok ? *(const float4*)(xp + c) : make_float4(0.f, 0.f, 0.f, 0.f);
            unsigned* dst = &As[r * A_STRIDE + c];
            dst[0] = tf32r(v.x); dst[1] = tf32r(v.y);
            dst[2] = tf32r(v.z); dst[3] = tf32r(v.w);
        }
    }
    {   // B tile: 64 x 256 assembled from W rows [0:64) and [64:128)
#pragma unroll
        for (int it = 0; it < 16; it++) {
            int v = tid + 256 * it;          // 0..4095 float4 slots
            int k = v >> 6;
            int j0 = (v & 63) * 4;
            const float* src = (j0 < 128) ? (Wm + k * 128 + j0)
                                          : (Wm + (64 + k) * 128 + (j0 - 128));
            float4 w4 = *(const float4*)src;
            unsigned* dst = &Bs[k * B_STRIDE + j0];
            dst[0] = tf32r(w4.x); dst[1] = tf32r(w4.y);
            dst[2] = tf32r(w4.z); dst[3] = tf32r(w4.w);
        }
    }
    __syncthreads();

    int wid = tid >> 5;
    int lane = tid & 31;
    int row0 = (wid >> 2) * 32;      // 0 or 32
    int col0 = (wid & 3) * 64;       // 0,64,128,192
    int lr = lane >> 2;              // 0..7
    int lc = lane & 3;               // 0..3

    float c[2][8][4];
#pragma unroll
    for (int mt = 0; mt < 2; mt++)
#pragma unroll
        for (int nt = 0; nt < 8; nt++)
#pragma unroll
            for (int e = 0; e < 4; e++) c[mt][nt][e] = 0.f;

#pragma unroll
    for (int k0 = 0; k0 < 64; k0 += 8) {
        unsigned a[2][4], b[8][2];
#pragma unroll
        for (int mt = 0; mt < 2; mt++) {
            int ra = row0 + mt * 16 + lr;
            a[mt][0] = As[ra * A_STRIDE + k0 + lc];
            a[mt][1] = As[(ra + 8) * A_STRIDE + k0 + lc];
            a[mt][2] = As[ra * A_STRIDE + k0 + lc + 4];
            a[mt][3] = As[(ra + 8) * A_STRIDE + k0 + lc + 4];
        }
#pragma unroll
        for (int nt = 0; nt < 8; nt++) {
            int cb = col0 + nt * 8 + lr;
            b[nt][0] = Bs[(k0 + lc) * B_STRIDE + cb];
            b[nt][1] = Bs[(k0 + lc + 4) * B_STRIDE + cb];
        }
#pragma unroll
        for (int mt = 0; mt < 2; mt++)
#pragma unroll
            for (int nt = 0; nt < 8; nt++)
                mma_tf32(c[mt][nt][0], c[mt][nt][1], c[mt][nt][2], c[mt][nt][3],
                         a[mt][0], a[mt][1], a[mt][2], a[mt][3],
                         b[nt][0], b[nt][1]);
    }

    bool is_q = (col0 < 128);
#pragma unroll
    for (int mt = 0; mt < 2; mt++) {
        int r_lo = blk_row0 + row0 + mt * 16 + lr;
        int r_hi = r_lo + 8;
#pragma unroll
        for (int nt = 0; nt < 8; nt++) {
            int cc = col0 + nt * 8 + 2 * lc;
            if (is_q) {
                float2 bb = *(const float2*)&bv[cc];
                if (r_lo < N)
                    *(float2*)&d_q[(size_t)r_lo * 128 + cc] =
                        make_float2(c[mt][nt][0] + bb.x, c[mt][nt][1] + bb.y);
                if (r_hi < N)
                    *(float2*)&d_q[(size_t)r_hi * 128 + cc] =
                        make_float2(c[mt][nt][2] + bb.x, c[mt][nt][3] + bb.y);
            } else {
                int cp = cc - 128;
                if (r_lo < N) {
                    __half2 h = __floats2half2_rn(c[mt][nt][0], c[mt][nt][1]);
                    *(unsigned*)&d_pv[(size_t)r_lo * 128 + cp] = *(unsigned*)&h;
                }
                if (r_hi < N) {
                    __half2 h = __floats2half2_rn(c[mt][nt][2], c[mt][nt][3]);
                    *(unsigned*)&d_pv[(size_t)r_hi * 128 + cp] = *(unsigned*)&h;
                }
            }
        }
    }
}

// ---------------- edge aggregation: one warp per target, 4-edge batched ----------------
__device__ __forceinline__ void fma4(float4& acc, float g, const float4& wv) {
    acc.x = fmaf(g, wv.x, acc.x);
    acc.y = fmaf(g, wv.y, acc.y);
    acc.z = fmaf(g, wv.z, acc.z);
    acc.w = fmaf(g, wv.w, acc.w);
}

__device__ __forceinline__ float4 max4(float4 a, float4 b) {
    return make_float4(fmaxf(a.x, b.x), fmaxf(a.y, b.y),
                       fmaxf(a.z, b.z), fmaxf(a.w, b.w));
}

__global__ void k_agg(const float* __restrict__ Wm, int N) {
    int w = (blockIdx.x * blockDim.x + threadIdx.x) >> 5;
    if (w >= N) return;
    int cnt = d_cnt[w];
    if (cnt == 0) return;
    int lane = threadIdx.x & 31;
    int start = d_off[w];
    int end = start + cnt;
    int col = lane * 4;

    float4 w0 = *(const float4*)&Wm[128 * 128 + col];   // ppf weight rows
    float4 w1 = *(const float4*)&Wm[129 * 128 + col];
    float4 w2 = *(const float4*)&Wm[130 * 128 + col];
    float4 w3 = *(const float4*)&Wm[131 * 128 + col];
    float4 m = make_float4(-3e38f, -3e38f, -3e38f, -3e38f);

    for (int base = start; base < end; base += 32) {
        int j = base + lane;
        int s = 0;
        uint2 pf = make_uint2(0u, 0u);
        if (j < end) {
            s = d_src[j];           // coalesced
            pf = d_ppf[j];          // coalesced 8B
        }
        int c32 = end - base;
        if (c32 > 32) c32 = 32;
        int i = 0;
        // ---- 4-edge batches: shfl+LDG issued up front, then FMA block ----
        for (; i + 4 <= c32; i += 4) {
            uint2 pvv[4];
            float2 ga[4], gb[4];
#pragma unroll
            for (int u = 0; u < 4; u++) {
                int si = __shfl_sync(0xffffffffu, s, i + u);
                unsigned hx = __shfl_sync(0xffffffffu, pf.x, i + u);
                unsigned hy = __shfl_sync(0xffffffffu, pf.y, i + u);
                pvv[u] = *(const uint2*)&d_pv[(size_t)si * 128 + col];
                ga[u] = __half22float2(*(__half2*)&hx);   // f0,f1
                gb[u] = __half22float2(*(__half2*)&hy);   // f2,f3
            }
            float4 z[4];
#pragma unroll
            for (int u = 0; u < 4; u++) {
                float2 p01 = __half22float2(*(__half2*)&pvv[u].x);
                float2 p23 = __half22float2(*(__half2*)&pvv[u].y);
                z[u] = make_float4(p01.x, p01.y, p23.x, p23.y);
                fma4(z[u], ga[u].x, w0);
                fma4(z[u], ga[u].y, w1);
                fma4(z[u], gb[u].x, w2);
                fma4(z[u], gb[u].y, w3);
            }
            m = max4(m, max4(max4(z[0], z[1]), max4(z[2], z[3])));
        }
        // ---- remainder ----
        for (; i < c32; i++) {
            int si = __shfl_sync(0xffffffffu, s, i);
            unsigned hx = __shfl_sync(0xffffffffu, pf.x, i);
            unsigned hy = __shfl_sync(0xffffffffu, pf.y, i);
            uint2 hv = *(const uint2*)&d_pv[(size_t)si * 128 + col];
            float2 ga = __half22float2(*(__half2*)&hx);
            float2 gb = __half22float2(*(__half2*)&hy);
            float2 p01 = __half22float2(*(__half2*)&hv.x);
            float2 p23 = __half22float2(*(__half2*)&hv.y);
            float4 z = make_float4(p01.x, p01.y, p23.x, p23.y);
            fma4(z, ga.x, w0);
            fma4(z, ga.y, w1);
            fma4(z, gb.x, w2);
            fma4(z, gb.y, w3);
            m = max4(m, z);
        }
    }
    float4 q = *(const float4*)&d_q[(size_t)w * 128 + col];
    m.x = fmaxf(q.x + m.x, 0.f);
    m.y = fmaxf(q.y + m.y, 0.f);
    m.z = fmaxf(q.z + m.z, 0.f);
    m.w = fmaxf(q.w + m.w, 0.f);
    *(float4*)&d_agg[(size_t)w * 128 + col] = m;
}

// ---------------- gather: out[s] = agg[idx[s]] (0 if no edges), pos_out ----------------
__global__ void k_gather(const float* __restrict__ pos, const int* __restrict__ idx,
                         float* __restrict__ out, int S) {
    int s = blockIdx.x;
    int h = threadIdx.x;  // 128
    int t = idx[s];
    float v = d_cnt[t] ? d_agg[(size_t)t * 128 + h] : 0.f;
    out[(size_t)s * 128 + h] = v;
    if (h < 3) out[(size_t)S * 128 + (size_t)s * 3 + h] = pos[3 * t + h];
}

// ---------------- launch (gemm on side stream || sort chain) ----------------
extern "C" void kernel_launch(void* const* d_in, const int* in_sizes, int n_in,
                              void* d_out, int out_size) {
    const float *x = 0, *pos = 0, *nor = 0, *Wm = 0, *bv = 0;
    const int *edge = 0, *idx = 0;
    for (int i = 0; i < n_in; i++) {
        int sz = in_sizes[i];
        if (sz == NODES * FEAT) x = (const float*)d_in[i];
        else if (sz == NODES * 3) { if (!pos) pos = (const float*)d_in[i]; else nor = (const float*)d_in[i]; }
        else if (sz == (2 * FEAT + 4) * HID) Wm = (const float*)d_in[i];
        else if (sz == HID) bv = (const float*)d_in[i];
        else if (sz == 2 * EDGES) edge = (const int*)d_in[i];
        else if (sz == SAMP) idx = (const int*)d_in[i];
    }
    const int* ecol = edge;          // e0 (sources)
    const int* erow = edge + EDGES;  // e1 (targets)

    static cudaStream_t sB = 0;
    static cudaEvent_t eFork = 0, ePv = 0;
    if (!sB) {
        cudaStreamCreateWithFlags(&sB, cudaStreamNonBlocking);
        cudaEventCreateWithFlags(&eFork, cudaEventDisableTiming);
        cudaEventCreateWithFlags(&ePv,   cudaEventDisableTiming);
        cudaFuncSetAttribute(k_gemm, cudaFuncAttributeMaxDynamicSharedMemorySize, GEMM_SMEM);
    }

    int nb = (NODES + 1023) / 1024;

    // fork: tensor-core gemm on sB, independent of the sort chain
    cudaEventRecord(eFork, 0);
    cudaStreamWaitEvent(sB, eFork, 0);
    k_gemm<<<(NODES + 63) / 64, 256, GEMM_SMEM, sB>>>(x, Wm, bv, NODES);
    cudaEventRecord(ePv, sB);

    // sort chain on the main stream (scatter now also computes+stores ppf)
    k_zero_cnt<<<(NODES + 255) / 256, 256>>>(NODES);
    k_hist<<<(EDGES + 255) / 256, 256>>>(erow, EDGES);
    k_scan1<<<nb, 1024>>>(NODES);
    k_scan2<<<1, 128>>>(nb);
    k_scan3<<<(NODES + 255) / 256, 256>>>(NODES);
    k_scatter<<<(EDGES + 255) / 256, 256>>>(ecol, erow, pos, nor, EDGES);

    // join: agg needs scatter (main) + gemm (sB)
    cudaStreamWaitEvent(0, ePv, 0);
    k_agg<<<(NODES + 7) / 8, 256>>>(Wm, NODES);
    k_gather<<<SAMP, 128>>>(pos, idx, (float*)d_out, SAMP);
}

// round 13
// speedup vs baseline: 1.1554x; 1.0658x over previous
#include <cuda_runtime.h>
#include <cuda_fp16.h>
#include <math.h>

// ---------------- problem constants (fixed by the dataset) ----------------
#define NODES 100000
#define FEAT  64
#define EDGES 800000
#define SAMP  25000
#define HID   128

// ---------------- scratch (device globals; no allocation) ----------------
__device__ float  d_q [(size_t)NODES * 128];   // W1^T x + b  (fp32)
__device__ __half d_pv[(size_t)NODES * 128];   // W2^T x      (fp16, hot random stream)
__device__ float  d_agg[(size_t)NODES * 128];  // per-node max-aggregated activations
__device__ int    d_cnt[NODES];
__device__ int    d_off[NODES];
__device__ int    d_cur[NODES];
__device__ int    d_src[EDGES];
__device__ uint2  d_ppfu[EDGES];               // packed half4 ppf, edge order
__device__ uint2  d_ppf[EDGES];                // packed half4 ppf, sorted by target
__device__ int    d_bsum[128];

// ---------------- counting sort of edges by target node ----------------
__global__ void k_zero_cnt(int n) {
    int i = blockIdx.x * blockDim.x + threadIdx.x;
    if (i < n) d_cnt[i] = 0;
}

__global__ void k_hist(const int* __restrict__ row, int E) {
    int i = blockIdx.x * blockDim.x + threadIdx.x;
    if (i < E) atomicAdd(&d_cnt[row[i]], 1);
}

__global__ void k_scan1(int n) {  // per-1024-block inclusive scan, block sums out
    __shared__ int sm[1024];
    int i = blockIdx.x * 1024 + threadIdx.x;
    int v = (i < n) ? d_cnt[i] : 0;
    sm[threadIdx.x] = v;
    __syncthreads();
    for (int d = 1; d < 1024; d <<= 1) {
        int t = 0;
        if (threadIdx.x >= d) t = sm[threadIdx.x - d];
        __syncthreads();
        if (threadIdx.x >= d) sm[threadIdx.x] += t;
        __syncthreads();
    }
    if (i < n) d_off[i] = sm[threadIdx.x];            // inclusive for now
    if (threadIdx.x == 1023) d_bsum[blockIdx.x] = sm[1023];
}

__global__ void k_scan2(int nb) {  // exclusive scan of <=128 block sums (1 block)
    __shared__ int sm[128];
    int t = threadIdx.x;
    int v = (t < nb) ? d_bsum[t] : 0;
    sm[t] = v;
    __syncthreads();
    for (int d = 1; d < 128; d <<= 1) {
        int u = 0;
        if (t >= d) u = sm[t - d];
        __syncthreads();
        if (t >= d) sm[t] += u;
        __syncthreads();
    }
    if (t < nb) d_bsum[t] = sm[t] - v;  // exclusive
}

__global__ void k_scan3(int n) {  // finalize exclusive offsets + scatter cursor
    int i = blockIdx.x * blockDim.x + threadIdx.x;
    if (i < n) {
        int e = d_off[i] - d_cnt[i] + d_bsum[i >> 10];
        d_off[i] = e;
        d_cur[i] = e;
    }
}

// ---------------- ppf compute (edge-parallel, unsorted; runs on side stream) ---------
__device__ __forceinline__ float angle3(float ax, float ay, float az,
                                        float bx, float by, float bz) {
    float cx = ay * bz - az * by;
    float cy = az * bx - ax * bz;
    float cz = ax * by - ay * bx;
    float cn = sqrtf(cx * cx + cy * cy + cz * cz);
    float d = ax * bx + ay * by + az * bz;
    return atan2f(cn, d);
}

__global__ void k_ppf(const int* __restrict__ col, const int* __restrict__ row,
                      const float* __restrict__ pos, const float* __restrict__ nor,
                      int E) {
    int i = blockIdx.x * blockDim.x + threadIdx.x;
    if (i >= E) return;
    int t = row[i];
    int s = col[i];
    float px = pos[3 * s]     - pos[3 * t];
    float py = pos[3 * s + 1] - pos[3 * t + 1];
    float pz = pos[3 * s + 2] - pos[3 * t + 2];
    float nsx = nor[3 * s], nsy = nor[3 * s + 1], nsz = nor[3 * s + 2];
    float ntx = nor[3 * t], nty = nor[3 * t + 1], ntz = nor[3 * t + 2];
    float f0 = sqrtf(px * px + py * py + pz * pz);
    float f1 = angle3(ntx, nty, ntz, px, py, pz);    // angle(n1, pseudo)
    float f2 = angle3(nsx, nsy, nsz, px, py, pz);    // angle(n0, pseudo)
    float f3 = angle3(ntx, nty, ntz, nsx, nsy, nsz); // angle(n1, n0)
    __half2 h01 = __floats2half2_rn(f0, f1);
    __half2 h23 = __floats2half2_rn(f2, f3);
    d_ppfu[i] = make_uint2(*(unsigned*)&h01, *(unsigned*)&h23);
}

// ---------------- scatter: pure permutation (ppf precomputed) -------------------------
__global__ void k_scatter(const int* __restrict__ col, const int* __restrict__ row, int E) {
    int i = blockIdx.x * blockDim.x + threadIdx.x;
    if (i < E) {
        int t = row[i];
        int p = atomicAdd(&d_cur[t], 1);
        d_src[p] = col[i];
        d_ppf[p] = d_ppfu[i];
    }
}

// ---------------- fused tf32 tensor-core GEMM: [64-row tile, K=64] x [64, 256] --------
// B[k][j] = (j<128) ? W[k][j] : W[64+k][j-128].
// cols 0..127 -> d_q (fp32, +bias), cols 128..255 -> d_pv (fp16).
#define A_STRIDE 68
#define B_STRIDE 264
#define GEMM_SMEM ((64 * A_STRIDE + 64 * B_STRIDE) * 4)

__device__ __forceinline__ unsigned tf32r(float f) {
    unsigned u;
    asm("cvt.rna.tf32.f32 %0, %1;" : "=r"(u) : "f"(f));
    return u;
}

__device__ __forceinline__ void mma_tf32(float& c0, float& c1, float& c2, float& c3,
                                         unsigned a0, unsigned a1, unsigned a2, unsigned a3,
                                         unsigned b0, unsigned b1) {
    asm volatile(
        "mma.sync.aligned.m16n8k8.row.col.f32.tf32.tf32.f32 "
        "{%0,%1,%2,%3}, {%4,%5,%6,%7}, {%8,%9}, {%0,%1,%2,%3};"
        : "+f"(c0), "+f"(c1), "+f"(c2), "+f"(c3)
        : "r"(a0), "r"(a1), "r"(a2), "r"(a3), "r"(b0), "r"(b1));
}

__global__ void __launch_bounds__(256)
k_gemm(const float* __restrict__ x, const float* __restrict__ Wm,
       const float* __restrict__ bv, int N) {
    extern __shared__ unsigned smem[];
    unsigned* As = smem;                     // [64][A_STRIDE]
    unsigned* Bs = smem + 64 * A_STRIDE;     // [64][B_STRIDE]
    int tid = threadIdx.x;
    int blk_row0 = blockIdx.x * 64;

    {   // A tile: 64 rows x 64 feats, tf32-rounded, row-major
        int r = tid >> 2;
        bool ok = (blk_row0 + r) < N;
        const float* xp = x + (size_t)(blk_row0 + r) * FEAT;
#pragma unroll
        for (int i = 0; i < 4; i++) {
            int c = (tid & 3) * 16 + i * 4;
            float4 v = ok ? *(const float4*)(xp + c) : make_float4(0.f, 0.f, 0.f, 0.f);
            unsigned* dst = &As[r * A_STRIDE + c];
            dst[0] = tf32r(v.x); dst[1] = tf32r(v.y);
            dst[2] = tf32r(v.z); dst[3] = tf32r(v.w);
        }
    }
    {   // B tile: 64 x 256 assembled from W rows [0:64) and [64:128)
#pragma unroll
        for (int it = 0; it < 16; it++) {
            int v = tid + 256 * it;          // 0..4095 float4 slots
            int k = v >> 6;
            int j0 = (v & 63) * 4;
            const float* src = (j0 < 128) ? (Wm + k * 128 + j0)
                                          : (Wm + (64 + k) * 128 + (j0 - 128));
            float4 w4 = *(const float4*)src;
            unsigned* dst = &Bs[k * B_STRIDE + j0];
            dst[0] = tf32r(w4.x); dst[1] = tf32r(w4.y);
            dst[2] = tf32r(w4.z); dst[3] = tf32r(w4.w);
        }
    }
    __syncthreads();

    int wid = tid >> 5;
    int lane = tid & 31;
    int row0 = (wid >> 2) * 32;      // 0 or 32
    int col0 = (wid & 3) * 64;       // 0,64,128,192
    int lr = lane >> 2;              // 0..7
    int lc = lane & 3;               // 0..3

    float c[2][8][4];
#pragma unroll
    for (int mt = 0; mt < 2; mt++)
#pragma unroll
        for (int nt = 0; nt < 8; nt++)
#pragma unroll
            for (int e = 0; e < 4; e++) c[mt][nt][e] = 0.f;

#pragma unroll
    for (int k0 = 0; k0 < 64; k0 += 8) {
        unsigned a[2][4], b[8][2];
#pragma unroll
        for (int mt = 0; mt < 2; mt++) {
            int ra = row0 + mt * 16 + lr;
            a[mt][0] = As[ra * A_STRIDE + k0 + lc];
            a[mt][1] = As[(ra + 8) * A_STRIDE + k0 + lc];
            a[mt][2] = As[ra * A_STRIDE + k0 + lc + 4];
            a[mt][3] = As[(ra + 8) * A_STRIDE + k0 + lc + 4];
        }
#pragma unroll
        for (int nt = 0; nt < 8; nt++) {
            int cb = col0 + nt * 8 + lr;
            b[nt][0] = Bs[(k0 + lc) * B_STRIDE + cb];
            b[nt][1] = Bs[(k0 + lc + 4) * B_STRIDE + cb];
        }
#pragma unroll
        for (int mt = 0; mt < 2; mt++)
#pragma unroll
            for (int nt = 0; nt < 8; nt++)
                mma_tf32(c[mt][nt][0], c[mt][nt][1], c[mt][nt][2], c[mt][nt][3],
                         a[mt][0], a[mt][1], a[mt][2], a[mt][3],
                         b[nt][0], b[nt][1]);
    }

    bool is_q = (col0 < 128);
#pragma unroll
    for (int mt = 0; mt < 2; mt++) {
        int r_lo = blk_row0 + row0 + mt * 16 + lr;
        int r_hi = r_lo + 8;
#pragma unroll
        for (int nt = 0; nt < 8; nt++) {
            int cc = col0 + nt * 8 + 2 * lc;
            if (is_q) {
                float2 bb = *(const float2*)&bv[cc];
                if (r_lo < N)
                    *(float2*)&d_q[(size_t)r_lo * 128 + cc] =
                        make_float2(c[mt][nt][0] + bb.x, c[mt][nt][1] + bb.y);
                if (r_hi < N)
                    *(float2*)&d_q[(size_t)r_hi * 128 + cc] =
                        make_float2(c[mt][nt][2] + bb.x, c[mt][nt][3] + bb.y);
            } else {
                int cp = cc - 128;
                if (r_lo < N) {
                    __half2 h = __floats2half2_rn(c[mt][nt][0], c[mt][nt][1]);
                    *(unsigned*)&d_pv[(size_t)r_lo * 128 + cp] = *(unsigned*)&h;
                }
                if (r_hi < N) {
                    __half2 h = __floats2half2_rn(c[mt][nt][2], c[mt][nt][3]);
                    *(unsigned*)&d_pv[(size_t)r_hi * 128 + cp] = *(unsigned*)&h;
                }
            }
        }
    }
}

// ---------------- edge aggregation: one warp per target, half2 math -------------------
__global__ void k_agg(const float* __restrict__ Wm, int N) {
    int w = (blockIdx.x * blockDim.x + threadIdx.x) >> 5;
    if (w >= N) return;
    int cnt = d_cnt[w];
    if (cnt == 0) return;
    int lane = threadIdx.x & 31;
    int start = d_off[w];
    int end = start + cnt;
    int col = lane * 4;

    float4 w0f = *(const float4*)&Wm[128 * 128 + col];   // ppf weight rows
    float4 w1f = *(const float4*)&Wm[129 * 128 + col];
    float4 w2f = *(const float4*)&Wm[130 * 128 + col];
    float4 w3f = *(const float4*)&Wm[131 * 128 + col];
    __half2 w0a = __floats2half2_rn(w0f.x, w0f.y), w0b = __floats2half2_rn(w0f.z, w0f.w);
    __half2 w1a = __floats2half2_rn(w1f.x, w1f.y), w1b = __floats2half2_rn(w1f.z, w1f.w);
    __half2 w2a = __floats2half2_rn(w2f.x, w2f.y), w2b = __floats2half2_rn(w2f.z, w2f.w);
    __half2 w3a = __floats2half2_rn(w3f.x, w3f.y), w3b = __floats2half2_rn(w3f.z, w3f.w);

    const __half2 NEGINF = __half2half2(__ushort_as_half(0xFC00));
    __half2 m0 = NEGINF, m1 = NEGINF;

    for (int base = start; base < end; base += 32) {
        int j = base + lane;
        int s = 0;
        uint2 pf = make_uint2(0u, 0u);
        if (j < end) {
            s = d_src[j];           // coalesced
            pf = d_ppf[j];          // coalesced 8B
        }
        int c32 = end - base;
        if (c32 > 32) c32 = 32;
        int i = 0;
        // ---- 4-edge batches: shfl+LDG issued up front, then HFMA2 block ----
        for (; i + 4 <= c32; i += 4) {
            uint2 pvv[4];
            unsigned gx[4], gy[4];
#pragma unroll
            for (int u = 0; u < 4; u++) {
                int si = __shfl_sync(0xffffffffu, s, i + u);
                gx[u] = __shfl_sync(0xffffffffu, pf.x, i + u);
                gy[u] = __shfl_sync(0xffffffffu, pf.y, i + u);
                pvv[u] = *(const uint2*)&d_pv[(size_t)si * 128 + col];
            }
            __half2 z0[4], z1[4];
#pragma unroll
            for (int u = 0; u < 4; u++) {
                __half2 hx = *(__half2*)&gx[u];       // (f0, f1)
                __half2 hy = *(__half2*)&gy[u];       // (f2, f3)
                __half2 g0 = __low2half2(hx),  g1 = __high2half2(hx);
                __half2 g2 = __low2half2(hy),  g3 = __high2half2(hy);
                __half2 p01 = *(__half2*)&pvv[u].x;
                __half2 p23 = *(__half2*)&pvv[u].y;
                z0[u] = __hfma2(g0, w0a, p01);  z1[u] = __hfma2(g0, w0b, p23);
                z0[u] = __hfma2(g1, w1a, z0[u]); z1[u] = __hfma2(g1, w1b, z1[u]);
                z0[u] = __hfma2(g2, w2a, z0[u]); z1[u] = __hfma2(g2, w2b, z1[u]);
                z0[u] = __hfma2(g3, w3a, z0[u]); z1[u] = __hfma2(g3, w3b, z1[u]);
            }
            m0 = __hmax2(m0, __hmax2(__hmax2(z0[0], z0[1]), __hmax2(z0[2], z0[3])));
            m1 = __hmax2(m1, __hmax2(__hmax2(z1[0], z1[1]), __hmax2(z1[2], z1[3])));
        }
        // ---- remainder ----
        for (; i < c32; i++) {
            int si = __shfl_sync(0xffffffffu, s, i);
            unsigned hxu = __shfl_sync(0xffffffffu, pf.x, i);
            unsigned hyu = __shfl_sync(0xffffffffu, pf.y, i);
            uint2 hv = *(const uint2*)&d_pv[(size_t)si * 128 + col];
            __half2 hx = *(__half2*)&hxu;
            __half2 hy = *(__half2*)&hyu;
            __half2 g0 = __low2half2(hx),  g1 = __high2half2(hx);
            __half2 g2 = __low2half2(hy),  g3 = __high2half2(hy);
            __half2 p01 = *(__half2*)&hv.x;
            __half2 p23 = *(__half2*)&hv.y;
            __half2 z0 = __hfma2(g0, w0a, p01);
            __half2 z1 = __hfma2(g0, w0b, p23);
            z0 = __hfma2(g1, w1a, z0); z1 = __hfma2(g1, w1b, z1);
            z0 = __hfma2(g2, w2a, z0); z1 = __hfma2(g2, w2b, z1);
            z0 = __hfma2(g3, w3a, z0); z1 = __hfma2(g3, w3b, z1);
            m0 = __hmax2(m0, z0);
            m1 = __hmax2(m1, z1);
        }
    }
    float2 a = __half22float2(m0);
    float2 b = __half22float2(m1);
    float4 q = *(const float4*)&d_q[(size_t)w * 128 + col];
    float4 r;
    r.x = fmaxf(q.x + a.x, 0.f);
    r.y = fmaxf(q.y + a.y, 0.f);
    r.z = fmaxf(q.z + b.x, 0.f);
    r.w = fmaxf(q.w + b.y, 0.f);
    *(float4*)&d_agg[(size_t)w * 128 + col] = r;
}

// ---------------- gather: out[s] = agg[idx[s]] (0 if no edges), pos_out ----------------
__global__ void k_gather(const float* __restrict__ pos, const int* __restrict__ idx,
                         float* __restrict__ out, int S) {
    int s = blockIdx.x;
    int h = threadIdx.x;  // 128
    int t = idx[s];
    float v = d_cnt[t] ? d_agg[(size_t)t * 128 + h] : 0.f;
    out[(size_t)s * 128 + h] = v;
    if (h < 3) out[(size_t)S * 128 + (size_t)s * 3 + h] = pos[3 * t + h];
}

// ---------------- launch (gemm+ppf on side stream || sort chain) ----------------------
extern "C" void kernel_launch(void* const* d_in, const int* in_sizes, int n_in,
                              void* d_out, int out_size) {
    const float *x = 0, *pos = 0, *nor = 0, *Wm = 0, *bv = 0;
    const int *edge = 0, *idx = 0;
    for (int i = 0; i < n_in; i++) {
        int sz = in_sizes[i];
        if (sz == NODES * FEAT) x = (const float*)d_in[i];
        else if (sz == NODES * 3) { if (!pos) pos = (const float*)d_in[i]; else nor = (const float*)d_in[i]; }
        else if (sz == (2 * FEAT + 4) * HID) Wm = (const float*)d_in[i];
        else if (sz == HID) bv = (const float*)d_in[i];
        else if (sz == 2 * EDGES) edge = (const int*)d_in[i];
        else if (sz == SAMP) idx = (const int*)d_in[i];
    }
    const int* ecol = edge;          // e0 (sources)
    const int* erow = edge + EDGES;  // e1 (targets)

    static cudaStream_t sB = 0;
    static cudaEvent_t eFork = 0, ePv = 0, ePpf = 0;
    if (!sB) {
        cudaStreamCreateWithFlags(&sB, cudaStreamNonBlocking);
        cudaEventCreateWithFlags(&eFork, cudaEventDisableTiming);
        cudaEventCreateWithFlags(&ePv,   cudaEventDisableTiming);
        cudaEventCreateWithFlags(&ePpf,  cudaEventDisableTiming);
        cudaFuncSetAttribute(k_gemm, cudaFuncAttributeMaxDynamicSharedMemorySize, GEMM_SMEM);
    }

    int nb = (NODES + 1023) / 1024;

    // fork: tensor-core gemm + ppf compute on sB, independent of the sort chain
    cudaEventRecord(eFork, 0);
    cudaStreamWaitEvent(sB, eFork, 0);
    k_gemm<<<(NODES + 63) / 64, 256, GEMM_SMEM, sB>>>(x, Wm, bv, NODES);
    cudaEventRecord(ePv, sB);
    k_ppf<<<(EDGES + 255) / 256, 256, 0, sB>>>(ecol, erow, pos, nor, EDGES);
    cudaEventRecord(ePpf, sB);

    // sort chain on the main stream
    k_zero_cnt<<<(NODES + 255) / 256, 256>>>(NODES);
    k_hist<<<(EDGES + 255) / 256, 256>>>(erow, EDGES);
    k_scan1<<<nb, 1024>>>(NODES);
    k_scan2<<<1, 128>>>(nb);
    k_scan3<<<(NODES + 255) / 256, 256>>>(NODES);
    cudaStreamWaitEvent(0, ePpf, 0);   // scatter permutes d_ppfu
    k_scatter<<<(EDGES + 255) / 256, 256>>>(ecol, erow, EDGES);

    // join: agg needs scatter (main) + gemm (sB)
    cudaStreamWaitEvent(0, ePv, 0);
    k_agg<<<(NODES + 7) / 8, 256>>>(Wm, NODES);
    k_gather<<<SAMP, 128>>>(pos, idx, (float*)d_out, SAMP);
}

// round 14
// speedup vs baseline: 1.2611x; 1.0914x over previous
#include <cuda_runtime.h>
#include <cuda_fp16.h>
#include <math.h>

// ---------------- problem constants (fixed by the dataset) ----------------
#define NODES 100000
#define FEAT  64
#define EDGES 800000
#define SAMP  25000
#define HID   128

// ---------------- scratch (device globals; no allocation) ----------------
__device__ float  d_q [(size_t)NODES * 128];   // W1^T x + b  (fp32)
__device__ __half d_pv[(size_t)NODES * 128];   // W2^T x      (fp16, hot random stream)
__device__ float  d_agg[(size_t)NODES * 128];  // per-node max-aggregated activations
__device__ int    d_cnt[NODES];
__device__ int    d_off[NODES];
__device__ int    d_cur[NODES];
__device__ int    d_src[EDGES];
__device__ uint2  d_ppfu[EDGES];               // packed half4 ppf, edge order
__device__ uint2  d_ppf[EDGES];                // packed half4 ppf, sorted by target
__device__ int    d_bsum[128];
__device__ int    d_tlist[NODES];              // compact list of nodes with cnt>0
__device__ int    d_ntl;                       // its length (<= SAMP)

// ---------------- counting sort of edges by target node ----------------
__global__ void k_zero_cnt(int n) {
    int i = blockIdx.x * blockDim.x + threadIdx.x;
    if (i < n) d_cnt[i] = 0;
    if (i == 0) d_ntl = 0;
}

__global__ void k_hist(const int* __restrict__ row, int E) {
    int i = blockIdx.x * blockDim.x + threadIdx.x;
    if (i < E) atomicAdd(&d_cnt[row[i]], 1);
}

__global__ void k_scan1(int n) {  // per-1024-block inclusive scan, block sums out
    __shared__ int sm[1024];
    int i = blockIdx.x * 1024 + threadIdx.x;
    int v = (i < n) ? d_cnt[i] : 0;
    sm[threadIdx.x] = v;
    __syncthreads();
    for (int d = 1; d < 1024; d <<= 1) {
        int t = 0;
        if (threadIdx.x >= d) t = sm[threadIdx.x - d];
        __syncthreads();
        if (threadIdx.x >= d) sm[threadIdx.x] += t;
        __syncthreads();
    }
    if (i < n) d_off[i] = sm[threadIdx.x];            // inclusive for now
    if (threadIdx.x == 1023) d_bsum[blockIdx.x] = sm[1023];
}

__global__ void k_scan2(int nb) {  // exclusive scan of <=128 block sums (1 block)
    __shared__ int sm[128];
    int t = threadIdx.x;
    int v = (t < nb) ? d_bsum[t] : 0;
    sm[t] = v;
    __syncthreads();
    for (int d = 1; d < 128; d <<= 1) {
        int u = 0;
        if (t >= d) u = sm[t - d];
        __syncthreads();
        if (t >= d) sm[t] += u;
        __syncthreads();
    }
    if (t < nb) d_bsum[t] = sm[t] - v;  // exclusive
}

__global__ void k_scan3(int n) {  // finalize offsets + cursor + compact target list
    int i = blockIdx.x * blockDim.x + threadIdx.x;
    if (i < n) {
        int c = d_cnt[i];
        int e = d_off[i] - c + d_bsum[i >> 10];
        d_off[i] = e;
        d_cur[i] = e;
        if (c > 0) {                       // warp-uniform address -> REDUX-aggregated
            int p = atomicAdd(&d_ntl, 1);
            d_tlist[p] = i;
        }
    }
}

// ---------------- ppf compute (edge-parallel, unsorted; runs on side stream) ---------
__device__ __forceinline__ float angle3(float ax, float ay, float az,
                                        float bx, float by, float bz) {
    float cx = ay * bz - az * by;
    float cy = az * bx - ax * bz;
    float cz = ax * by - ay * bx;
    float cn = sqrtf(cx * cx + cy * cy + cz * cz);
    float d = ax * bx + ay * by + az * bz;
    return atan2f(cn, d);
}

__global__ void k_ppf(const int* __restrict__ col, const int* __restrict__ row,
                      const float* __restrict__ pos, const float* __restrict__ nor,
                      int E) {
    int i = blockIdx.x * blockDim.x + threadIdx.x;
    if (i >= E) return;
    int t = row[i];
    int s = col[i];
    float px = pos[3 * s]     - pos[3 * t];
    float py = pos[3 * s + 1] - pos[3 * t + 1];
    float pz = pos[3 * s + 2] - pos[3 * t + 2];
    float nsx = nor[3 * s], nsy = nor[3 * s + 1], nsz = nor[3 * s + 2];
    float ntx = nor[3 * t], nty = nor[3 * t + 1], ntz = nor[3 * t + 2];
    float f0 = sqrtf(px * px + py * py + pz * pz);
    float f1 = angle3(ntx, nty, ntz, px, py, pz);    // angle(n1, pseudo)
    float f2 = angle3(nsx, nsy, nsz, px, py, pz);    // angle(n0, pseudo)
    float f3 = angle3(ntx, nty, ntz, nsx, nsy, nsz); // angle(n1, n0)
    __half2 h01 = __floats2half2_rn(f0, f1);
    __half2 h23 = __floats2half2_rn(f2, f3);
    d_ppfu[i] = make_uint2(*(unsigned*)&h01, *(unsigned*)&h23);
}

// ---------------- scatter: pure permutation (ppf precomputed) -------------------------
__global__ void k_scatter(const int* __restrict__ col, const int* __restrict__ row, int E) {
    int i = blockIdx.x * blockDim.x + threadIdx.x;
    if (i < E) {
        int t = row[i];
        int p = atomicAdd(&d_cur[t], 1);
        d_src[p] = col[i];
        d_ppf[p] = d_ppfu[i];
    }
}

// ---------------- fused tf32 tensor-core GEMM: [64-row tile, K=64] x [64, 256] --------
// B[k][j] = (j<128) ? W[k][j] : W[64+k][j-128].
// cols 0..127 -> d_q (fp32, +bias), cols 128..255 -> d_pv (fp16).
#define A_STRIDE 68
#define B_STRIDE 264
#define GEMM_SMEM ((64 * A_STRIDE + 64 * B_STRIDE) * 4)

__device__ __forceinline__ unsigned tf32r(float f) {
    unsigned u;
    asm("cvt.rna.tf32.f32 %0, %1;" : "=r"(u) : "f"(f));
    return u;
}

__device__ __forceinline__ void mma_tf32(float& c0, float& c1, float& c2, float& c3,
                                         unsigned a0, unsigned a1, unsigned a2, unsigned a3,
                                         unsigned b0, unsigned b1) {
    asm volatile(
        "mma.sync.aligned.m16n8k8.row.col.f32.tf32.tf32.f32 "
        "{%0,%1,%2,%3}, {%4,%5,%6,%7}, {%8,%9}, {%0,%1,%2,%3};"
        : "+f"(c0), "+f"(c1), "+f"(c2), "+f"(c3)
        : "r"(a0), "r"(a1), "r"(a2), "r"(a3), "r"(b0), "r"(b1));
}

__global__ void __launch_bounds__(256)
k_gemm(const float* __restrict__ x, const float* __restrict__ Wm,
       const float* __restrict__ bv, int N) {
    extern __shared__ unsigned smem[];
    unsigned* As = smem;                     // [64][A_STRIDE]
    unsigned* Bs = smem + 64 * A_STRIDE;     // [64][B_STRIDE]
    int tid = threadIdx.x;
    int blk_row0 = blockIdx.x * 64;

    {   // A tile: 64 rows x 64 feats, tf32-rounded, row-major
        int r = tid >> 2;
        bool ok = (blk_row0 + r) < N;
        const float* xp = x + (size_t)(blk_row0 + r) * FEAT;
#pragma unroll
        for (int i = 0; i < 4; i++) {
            int c = (tid & 3) * 16 + i * 4;
            float4 v = ok ? *(const float4*)(xp + c) : make_float4(0.f, 0.f, 0.f, 0.f);
            unsigned* dst = &As[r * A_STRIDE + c];
            dst[0] = tf32r(v.x); dst[1] = tf32r(v.y);
            dst[2] = tf32r(v.z); dst[3] = tf32r(v.w);
        }
    }
    {   // B tile: 64 x 256 assembled from W rows [0:64) and [64:128)
#pragma unroll
        for (int it = 0; it < 16; it++) {
            int v = tid + 256 * it;          // 0..4095 float4 slots
            int k = v >> 6;
            int j0 = (v & 63) * 4;
            const float* src = (j0 < 128) ? (Wm + k * 128 + j0)
                                          : (Wm + (64 + k) * 128 + (j0 - 128));
            float4 w4 = *(const float4*)src;
            unsigned* dst = &Bs[k * B_STRIDE + j0];
            dst[0] = tf32r(w4.x); dst[1] = tf32r(w4.y);
            dst[2] = tf32r(w4.z); dst[3] = tf32r(w4.w);
        }
    }
    __syncthreads();

    int wid = tid >> 5;
    int lane = tid & 31;
    int row0 = (wid >> 2) * 32;      // 0 or 32
    int col0 = (wid & 3) * 64;       // 0,64,128,192
    int lr = lane >> 2;              // 0..7
    int lc = lane & 3;               // 0..3

    float c[2][8][4];
#pragma unroll
    for (int mt = 0; mt < 2; mt++)
#pragma unroll
        for (int nt = 0; nt < 8; nt++)
#pragma unroll
            for (int e = 0; e < 4; e++) c[mt][nt][e] = 0.f;

#pragma unroll
    for (int k0 = 0; k0 < 64; k0 += 8) {
        unsigned a[2][4], b[8][2];
#pragma unroll
        for (int mt = 0; mt < 2; mt++) {
            int ra = row0 + mt * 16 + lr;
            a[mt][0] = As[ra * A_STRIDE + k0 + lc];
            a[mt][1] = As[(ra + 8) * A_STRIDE + k0 + lc];
            a[mt][2] = As[ra * A_STRIDE + k0 + lc + 4];
            a[mt][3] = As[(ra + 8) * A_STRIDE + k0 + lc + 4];
        }
#pragma unroll
        for (int nt = 0; nt < 8; nt++) {
            int cb = col0 + nt * 8 + lr;
            b[nt][0] = Bs[(k0 + lc) * B_STRIDE + cb];
            b[nt][1] = Bs[(k0 + lc + 4) * B_STRIDE + cb];
        }
#pragma unroll
        for (int mt = 0; mt < 2; mt++)
#pragma unroll
            for (int nt = 0; nt < 8; nt++)
                mma_tf32(c[mt][nt][0], c[mt][nt][1], c[mt][nt][2], c[mt][nt][3],
                         a[mt][0], a[mt][1], a[mt][2], a[mt][3],
                         b[nt][0], b[nt][1]);
    }

    bool is_q = (col0 < 128);
#pragma unroll
    for (int mt = 0; mt < 2; mt++) {
        int r_lo = blk_row0 + row0 + mt * 16 + lr;
        int r_hi = r_lo + 8;
#pragma unroll
        for (int nt = 0; nt < 8; nt++) {
            int cc = col0 + nt * 8 + 2 * lc;
            if (is_q) {
                float2 bb = *(const float2*)&bv[cc];
                if (r_lo < N)
                    *(float2*)&d_q[(size_t)r_lo * 128 + cc] =
                        make_float2(c[mt][nt][0] + bb.x, c[mt][nt][1] + bb.y);
                if (r_hi < N)
                    *(float2*)&d_q[(size_t)r_hi * 128 + cc] =
                        make_float2(c[mt][nt][2] + bb.x, c[mt][nt][3] + bb.y);
            } else {
                int cp = cc - 128;
                if (r_lo < N) {
                    __half2 h = __floats2half2_rn(c[mt][nt][0], c[mt][nt][1]);
                    *(unsigned*)&d_pv[(size_t)r_lo * 128 + cp] = *(unsigned*)&h;
                }
                if (r_hi < N) {
                    __half2 h = __floats2half2_rn(c[mt][nt][2], c[mt][nt][3]);
                    *(unsigned*)&d_pv[(size_t)r_hi * 128 + cp] = *(unsigned*)&h;
                }
            }
        }
    }
}

// ---------------- edge aggregation: one warp per ACTIVE target (tlist), half2 math ----
__global__ void k_agg(const float* __restrict__ Wm) {
    int wg = (blockIdx.x * blockDim.x + threadIdx.x) >> 5;
    if (wg >= d_ntl) return;
    int w = d_tlist[wg];                 // cnt > 0 guaranteed
    int cnt = d_cnt[w];
    int lane = threadIdx.x & 31;
    int start = d_off[w];
    int end = start + cnt;
    int col = lane * 4;

    float4 w0f = *(const float4*)&Wm[128 * 128 + col];   // ppf weight rows
    float4 w1f = *(const float4*)&Wm[129 * 128 + col];
    float4 w2f = *(const float4*)&Wm[130 * 128 + col];
    float4 w3f = *(const float4*)&Wm[131 * 128 + col];
    __half2 w0a = __floats2half2_rn(w0f.x, w0f.y), w0b = __floats2half2_rn(w0f.z, w0f.w);
    __half2 w1a = __floats2half2_rn(w1f.x, w1f.y), w1b = __floats2half2_rn(w1f.z, w1f.w);
    __half2 w2a = __floats2half2_rn(w2f.x, w2f.y), w2b = __floats2half2_rn(w2f.z, w2f.w);
    __half2 w3a = __floats2half2_rn(w3f.x, w3f.y), w3b = __floats2half2_rn(w3f.z, w3f.w);

    const __half2 NEGINF = __half2half2(__ushort_as_half(0xFC00));
    __half2 m0 = NEGINF, m1 = NEGINF;

    for (int base = start; base < end; base += 32) {
        int j = base + lane;
        int s = 0;
        uint2 pf = make_uint2(0u, 0u);
        if (j < end) {
            s = d_src[j];           // coalesced
            pf = d_ppf[j];          // coalesced 8B
        }
        int c32 = end - base;
        if (c32 > 32) c32 = 32;
        int i = 0;
        // ---- 4-edge batches: shfl+LDG issued up front, then HFMA2 block ----
        for (; i + 4 <= c32; i += 4) {
            uint2 pvv[4];
            unsigned gx[4], gy[4];
#pragma unroll
            for (int u = 0; u < 4; u++) {
                int si = __shfl_sync(0xffffffffu, s, i + u);
                gx[u] = __shfl_sync(0xffffffffu, pf.x, i + u);
                gy[u] = __shfl_sync(0xffffffffu, pf.y, i + u);
                pvv[u] = *(const uint2*)&d_pv[(size_t)si * 128 + col];
            }
            __half2 z0[4], z1[4];
#pragma unroll
            for (int u = 0; u < 4; u++) {
                __half2 hx = *(__half2*)&gx[u];       // (f0, f1)
                __half2 hy = *(__half2*)&gy[u];       // (f2, f3)
                __half2 g0 = __low2half2(hx),  g1 = __high2half2(hx);
                __half2 g2 = __low2half2(hy),  g3 = __high2half2(hy);
                __half2 p01 = *(__half2*)&pvv[u].x;
                __half2 p23 = *(__half2*)&pvv[u].y;
                z0[u] = __hfma2(g0, w0a, p01);  z1[u] = __hfma2(g0, w0b, p23);
                z0[u] = __hfma2(g1, w1a, z0[u]); z1[u] = __hfma2(g1, w1b, z1[u]);
                z0[u] = __hfma2(g2, w2a, z0[u]); z1[u] = __hfma2(g2, w2b, z1[u]);
                z0[u] = __hfma2(g3, w3a, z0[u]); z1[u] = __hfma2(g3, w3b, z1[u]);
            }
            m0 = __hmax2(m0, __hmax2(__hmax2(z0[0], z0[1]), __hmax2(z0[2], z0[3])));
            m1 = __hmax2(m1, __hmax2(__hmax2(z1[0], z1[1]), __hmax2(z1[2], z1[3])));
        }
        // ---- remainder ----
        for (; i < c32; i++) {
            int si = __shfl_sync(0xffffffffu, s, i);
            unsigned hxu = __shfl_sync(0xffffffffu, pf.x, i);
            unsigned hyu = __shfl_sync(0xffffffffu, pf.y, i);
            uint2 hv = *(const uint2*)&d_pv[(size_t)si * 128 + col];
            __half2 hx = *(__half2*)&hxu;
            __half2 hy = *(__half2*)&hyu;
            __half2 g0 = __low2half2(hx),  g1 = __high2half2(hx);
            __half2 g2 = __low2half2(hy),  g3 = __high2half2(hy);
            __half2 p01 = *(__half2*)&hv.x;
            __half2 p23 = *(__half2*)&hv.y;
            __half2 z0 = __hfma2(g0, w0a, p01);
            __half2 z1 = __hfma2(g0, w0b, p23);
            z0 = __hfma2(g1, w1a, z0); z1 = __hfma2(g1, w1b, z1);
            z0 = __hfma2(g2, w2a, z0); z1 = __hfma2(g2, w2b, z1);
            z0 = __hfma2(g3, w3a, z0); z1 = __hfma2(g3, w3b, z1);
            m0 = __hmax2(m0, z0);
            m1 = __hmax2(m1, z1);
        }
    }
    float2 a = __half22float2(m0);
    float2 b = __half22float2(m1);
    float4 q = *(const float4*)&d_q[(size_t)w * 128 + col];
    float4 r;
    r.x = fmaxf(q.x + a.x, 0.f);
    r.y = fmaxf(q.y + a.y, 0.f);
    r.z = fmaxf(q.z + b.x, 0.f);
    r.w = fmaxf(q.w + b.y, 0.f);
    *(float4*)&d_agg[(size_t)w * 128 + col] = r;
}

// ---------------- gather: out[s] = agg[idx[s]] (0 if no edges), pos_out ----------------
__global__ void k_gather(const float* __restrict__ pos, const int* __restrict__ idx,
                         float* __restrict__ out, int S) {
    int s = blockIdx.x;
    int h = threadIdx.x;  // 128
    int t = idx[s];
    float v = d_cnt[t] ? d_agg[(size_t)t * 128 + h] : 0.f;
    out[(size_t)s * 128 + h] = v;
    if (h < 3) out[(size_t)S * 128 + (size_t)s * 3 + h] = pos[3 * t + h];
}

// ---------------- launch (gemm+ppf on side stream || sort chain) ----------------------
extern "C" void kernel_launch(void* const* d_in, const int* in_sizes, int n_in,
                              void* d_out, int out_size) {
    const float *x = 0, *pos = 0, *nor = 0, *Wm = 0, *bv = 0;
    const int *edge = 0, *idx = 0;
    for (int i = 0; i < n_in; i++) {
        int sz = in_sizes[i];
        if (sz == NODES * FEAT) x = (const float*)d_in[i];
        else if (sz == NODES * 3) { if (!pos) pos = (const float*)d_in[i]; else nor = (const float*)d_in[i]; }
        else if (sz == (2 * FEAT + 4) * HID) Wm = (const float*)d_in[i];
        else if (sz == HID) bv = (const float*)d_in[i];
        else if (sz == 2 * EDGES) edge = (const int*)d_in[i];
        else if (sz == SAMP) idx = (const int*)d_in[i];
    }
    const int* ecol = edge;          // e0 (sources)
    const int* erow = edge + EDGES;  // e1 (targets)

    static cudaStream_t sB = 0;
    static cudaEvent_t eFork = 0, ePv = 0, ePpf = 0;
    if (!sB) {
        cudaStreamCreateWithFlags(&sB, cudaStreamNonBlocking);
        cudaEventCreateWithFlags(&eFork, cudaEventDisableTiming);
        cudaEventCreateWithFlags(&ePv,   cudaEventDisableTiming);
        cudaEventCreateWithFlags(&ePpf,  cudaEventDisableTiming);
        cudaFuncSetAttribute(k_gemm, cudaFuncAttributeMaxDynamicSharedMemorySize, GEMM_SMEM);
    }

    int nb = (NODES + 1023) / 1024;

    // fork: tensor-core gemm + ppf compute on sB, independent of the sort chain
    cudaEventRecord(eFork, 0);
    cudaStreamWaitEvent(sB, eFork, 0);
    k_gemm<<<(NODES + 63) / 64, 256, GEMM_SMEM, sB>>>(x, Wm, bv, NODES);
    cudaEventRecord(ePv, sB);
    k_ppf<<<(EDGES + 255) / 256, 256, 0, sB>>>(ecol, erow, pos, nor, EDGES);
    cudaEventRecord(ePpf, sB);

    // sort chain on the main stream
    k_zero_cnt<<<(NODES + 255) / 256, 256>>>(NODES);
    k_hist<<<(EDGES + 255) / 256, 256>>>(erow, EDGES);
    k_scan1<<<nb, 1024>>>(NODES);
    k_scan2<<<1, 128>>>(nb);
    k_scan3<<<(NODES + 255) / 256, 256>>>(NODES);
    cudaStreamWaitEvent(0, ePpf, 0);   // scatter permutes d_ppfu
    k_scatter<<<(EDGES + 255) / 256, 256>>>(ecol, erow, EDGES);

    // join: agg needs scatter (main) + gemm (sB); one warp per active target
    cudaStreamWaitEvent(0, ePv, 0);
    k_agg<<<(SAMP + 7) / 8, 256>>>(Wm);
    k_gather<<<SAMP, 128>>>(pos, idx, (float*)d_out, SAMP);
}